// round 13
// baseline (speedup 1.0000x reference)
#include <cuda_runtime.h>
#include <cuda_bf16.h>
#include <math.h>
#include <stdint.h>

// DCGRU decoder: SEQ=32, B=1024, N=19, H=128, OUT=1, K=2 Chebyshev, 2 layers.
// R8 resubmit (R9 was an infra failure, kernel never ran):
// float4 cheby, MUFU fast-math epilogue, single fused init kernel.

#define BATCH 1024
#define NNODE 19
#define HID   128
#define ROWS  (BATCH * NNODE)   // 19456 = 304 * 64
#define SEQLEN 32

#define KP0 416                  // layer0 K: [h*3 (384) | x0 x1 x2 | pad]
#define K0R 387
#define KP1 768

#define WO_G0 0
#define WO_C0 (WO_G0 + 256 * KP0)
#define WO_G1 (WO_C0 + 128 * KP0)
#define WO_C1 (WO_G1 + 256 * KP1)
#define WTOT  (WO_C1 + 128 * KP1)

// ---------------- persistent device scratch ---------------------------------
__device__ float g_h0[ROWS * HID];
__device__ float g_h1[ROWS * HID];
__device__ float g_ru[ROWS * 256];          // [r*h | u]
__device__ __align__(16) __nv_bfloat16 g_X0h[ROWS * KP0];
__device__ __align__(16) __nv_bfloat16 g_X0l[ROWS * KP0];
__device__ __align__(16) __nv_bfloat16 g_X1h[ROWS * KP1];
__device__ __align__(16) __nv_bfloat16 g_X1l[ROWS * KP1];
__device__ __align__(16) __nv_bfloat16 g_Wh[WTOT];
__device__ __align__(16) __nv_bfloat16 g_Wl[WTOT];

// ---------------- helpers ----------------------------------------------------
__device__ __forceinline__ uint32_t smem_u32(const void* p) {
    uint32_t a;
    asm("{ .reg .u64 t; cvta.to.shared.u64 t, %1; cvt.u32.u64 %0, t; }" : "=r"(a) : "l"(p));
    return a;
}
__device__ __forceinline__ void cpasync16(uint32_t dst, const void* src) {
    asm volatile("cp.async.cg.shared.global [%0], [%1], 16;" :: "r"(dst), "l"(src) : "memory");
}
#define CP_COMMIT() asm volatile("cp.async.commit_group;" ::: "memory")
#define CP_WAIT(n)  asm volatile("cp.async.wait_group %0;" :: "n"(n) : "memory")

__device__ __forceinline__ void ldsm_x4(uint32_t* r, uint32_t addr) {
    asm volatile("ldmatrix.sync.aligned.m8n8.x4.shared.b16 {%0,%1,%2,%3}, [%4];"
                 : "=r"(r[0]), "=r"(r[1]), "=r"(r[2]), "=r"(r[3]) : "r"(addr));
}
__device__ __forceinline__ void mma_bf16(float* d, const uint32_t* a, const uint32_t* b) {
    asm volatile("mma.sync.aligned.m16n8k16.row.col.f32.bf16.bf16.f32 "
                 "{%0,%1,%2,%3},{%4,%5,%6,%7},{%8,%9},{%0,%1,%2,%3};"
                 : "+f"(d[0]), "+f"(d[1]), "+f"(d[2]), "+f"(d[3])
                 : "r"(a[0]), "r"(a[1]), "r"(a[2]), "r"(a[3]), "r"(b[0]), "r"(b[1]));
}
__device__ __forceinline__ uint32_t swz64(uint32_t o) { return o ^ ((o >> 3) & 0x30); }

__device__ __forceinline__ float fast_sig(float x) {
    return 1.f / (1.f + __expf(-x));
}
__device__ __forceinline__ float fast_tanh(float x) {
    float ax = fabsf(x);
    float t = 1.f - 2.f / (__expf(2.f * ax) + 1.f);
    return copysignf(t, x);
}

// store 4 fp32 as bf16 hi plane + bf16 residual plane (two 8B stores)
__device__ __forceinline__ void store4(__nv_bfloat16* __restrict__ H,
                                       __nv_bfloat16* __restrict__ L,
                                       size_t idx, float4 v) {
    __nv_bfloat162 h0 = __float22bfloat162_rn(make_float2(v.x, v.y));
    __nv_bfloat162 h1 = __float22bfloat162_rn(make_float2(v.z, v.w));
    uint2 hp;
    hp.x = *(uint32_t*)&h0; hp.y = *(uint32_t*)&h1;
    *(uint2*)(H + idx) = hp;
    float2 f0 = __bfloat1622float2(h0), f1 = __bfloat1622float2(h1);
    __nv_bfloat162 l0 = __float22bfloat162_rn(make_float2(v.x - f0.x, v.y - f0.y));
    __nv_bfloat162 l1 = __float22bfloat162_rn(make_float2(v.z - f1.x, v.w - f1.y));
    uint2 lp;
    lp.x = *(uint32_t*)&l0; lp.y = *(uint32_t*)&l1;
    *(uint2*)(L + idx) = lp;
}
__device__ __forceinline__ void store1(__nv_bfloat16* H, __nv_bfloat16* L,
                                       size_t idx, float v) {
    __nv_bfloat16 h = __float2bfloat16(v);
    H[idx] = h;
    L[idx] = __float2bfloat16(v - __bfloat162float(h));
}

// ---------------- fused init: h, X0 pad, all weight planes -------------------
#define NB_H    9728
#define NB_ZP   2205
#define NB_PG0  416
#define NB_PC0  208
#define NB_PG1  768
#define NB_PC1  384
#define NB_INIT (NB_H + NB_ZP + NB_PG0 + NB_PC0 + NB_PG1 + NB_PC1)

__device__ __forceinline__ void prep_one(const float* W, int off, bool perm,
                                         int KP_, int Nw, int i) {
    if (i >= Nw * KP_) return;
    int n = i / KP_, kk = i % KP_;
    float w;
    if (perm) {
        if (kk < 384)      w = W[((kk >> 7) * 129 + 1 + (kk & 127)) * Nw + n];
        else if (kk < 387) w = W[(kk - 384) * 129 * Nw + n];
        else               w = 0.f;
    } else {
        w = (kk < 768) ? W[kk * Nw + n] : 0.f;
    }
    __nv_bfloat16 h = __float2bfloat16(w);
    g_Wh[off + i] = h;
    g_Wl[off + i] = __float2bfloat16(w - __bfloat162float(h));
}

__global__ void k_init(const float* __restrict__ ih,
                       const float* __restrict__ Wg0, const float* __restrict__ Wc0,
                       const float* __restrict__ Wg1, const float* __restrict__ Wc1) {
    int blk = blockIdx.x, tid = threadIdx.x;
    if (blk < NB_H) {
        int i = blk * 256 + tid;
        if (i < ROWS * HID) { g_h0[i] = ih[i]; g_h1[i] = ih[ROWS * HID + i]; }
        return;
    }
    blk -= NB_H;
    if (blk < NB_ZP) {
        int i = blk * 256 + tid;
        const int PC = KP0 - K0R;   // 29
        if (i < ROWS * PC) {
            int row = i / PC, c = K0R + i % PC;
            g_X0h[(size_t)row * KP0 + c] = __float2bfloat16(0.f);
            g_X0l[(size_t)row * KP0 + c] = __float2bfloat16(0.f);
        }
        return;
    }
    blk -= NB_ZP;
    if (blk < NB_PG0) { prep_one(Wg0, WO_G0, true, KP0, 256, blk * 256 + tid); return; }
    blk -= NB_PG0;
    if (blk < NB_PC0) { prep_one(Wc0, WO_C0, true, KP0, 128, blk * 256 + tid); return; }
    blk -= NB_PC0;
    if (blk < NB_PG1) { prep_one(Wg1, WO_G1, false, KP1, 256, blk * 256 + tid); return; }
    blk -= NB_PG1;
    prep_one(Wc1, WO_C1, false, KP1, 128, blk * 256 + tid);
}

// ---------------- cheby kernels (float4 vectorized) --------------------------
__device__ __forceinline__ void load_S(const float* S, float* sS, float* sS2, int tid) {
    for (int i = tid; i < 361; i += 256) sS[i] = S[i];
    __syncthreads();
    for (int i = tid; i < 361; i += 256) {
        int m = i / NNODE, n = i % NNODE;
        float acc = 0.f;
#pragma unroll
        for (int k = 0; k < NNODE; k++) acc += sS[m * NNODE + k] * sS[k * NNODE + n];
        sS2[i] = 2.f * acc - (m == n ? 1.f : 0.f);
    }
}

// layer0 gate: h feats -> cols j*128+f; x feat -> 384+j.
__global__ void k_cheby0_gate(const float* __restrict__ S, const float* __restrict__ xprev) {
    __shared__ float4 s4[NNODE][32];
    __shared__ float sx[NNODE];
    __shared__ float sS[361], sS2[361];
    const int b = blockIdx.x, tid = threadIdx.x;

    load_S(S, sS, sS2, tid);
    for (int i = tid; i < NNODE * 32; i += 256) {
        int n = i >> 5, f4 = i & 31;
        s4[n][f4] = *(const float4*)(g_h0 + (size_t)(b * NNODE + n) * HID + 4 * f4);
    }
    if (tid < NNODE) sx[tid] = xprev ? xprev[b * NNODE + tid] : 0.f;
    __syncthreads();

    for (int p = tid; p < NNODE * 32; p += 256) {
        int m = p >> 5, f4 = p & 31;
        float4 x0 = s4[m][f4];
        float4 a1 = make_float4(0, 0, 0, 0), a2 = make_float4(0, 0, 0, 0);
#pragma unroll
        for (int n = 0; n < NNODE; n++) {
            float4 v = s4[n][f4];
            float w1 = sS[m * NNODE + n], w2 = sS2[m * NNODE + n];
            a1.x = fmaf(w1, v.x, a1.x); a1.y = fmaf(w1, v.y, a1.y);
            a1.z = fmaf(w1, v.z, a1.z); a1.w = fmaf(w1, v.w, a1.w);
            a2.x = fmaf(w2, v.x, a2.x); a2.y = fmaf(w2, v.y, a2.y);
            a2.z = fmaf(w2, v.z, a2.z); a2.w = fmaf(w2, v.w, a2.w);
        }
        size_t base = (size_t)(b * NNODE + m) * KP0 + 4 * f4;
        store4(g_X0h, g_X0l, base,       x0);
        store4(g_X0h, g_X0l, base + 128, a1);
        store4(g_X0h, g_X0l, base + 256, a2);
    }
    if (tid < NNODE) {
        int m = tid;
        float x0 = sx[m], a1 = 0.f, a2 = 0.f;
#pragma unroll
        for (int n = 0; n < NNODE; n++) {
            a1 = fmaf(sS[m * NNODE + n], sx[n], a1);
            a2 = fmaf(sS2[m * NNODE + n], sx[n], a2);
        }
        size_t base = (size_t)(b * NNODE + m) * KP0 + 384;
        store1(g_X0h, g_X0l, base, x0);
        store1(g_X0h, g_X0l, base + 1, a1);
        store1(g_X0h, g_X0l, base + 2, a2);
    }
}

// layer1 gate: src [h0|h1] (256 feats) -> cols j*256+f.
__global__ void k_cheby1_gate(const float* __restrict__ S) {
    __shared__ float4 s4[NNODE][64];
    __shared__ float sS[361], sS2[361];
    const int b = blockIdx.x, tid = threadIdx.x;

    load_S(S, sS, sS2, tid);
    for (int i = tid; i < NNODE * 64; i += 256) {
        int n = i >> 6, f4 = i & 63;
        size_t row = (size_t)(b * NNODE + n);
        s4[n][f4] = (f4 < 32)
            ? *(const float4*)(g_h0 + row * HID + 4 * f4)
            : *(const float4*)(g_h1 + row * HID + 4 * (f4 - 32));
    }
    __syncthreads();

    for (int p = tid; p < NNODE * 64; p += 256) {
        int m = p >> 6, f4 = p & 63;
        float4 x0 = s4[m][f4];
        float4 a1 = make_float4(0, 0, 0, 0), a2 = make_float4(0, 0, 0, 0);
#pragma unroll
        for (int n = 0; n < NNODE; n++) {
            float4 v = s4[n][f4];
            float w1 = sS[m * NNODE + n], w2 = sS2[m * NNODE + n];
            a1.x = fmaf(w1, v.x, a1.x); a1.y = fmaf(w1, v.y, a1.y);
            a1.z = fmaf(w1, v.z, a1.z); a1.w = fmaf(w1, v.w, a1.w);
            a2.x = fmaf(w2, v.x, a2.x); a2.y = fmaf(w2, v.y, a2.y);
            a2.z = fmaf(w2, v.z, a2.z); a2.w = fmaf(w2, v.w, a2.w);
        }
        size_t base = (size_t)(b * NNODE + m) * KP1 + 4 * f4;
        store4(g_X1h, g_X1l, base,       x0);
        store4(g_X1h, g_X1l, base + 256, a1);
        store4(g_X1h, g_X1l, base + 512, a2);
    }
}

// cand cheby: src r*h (g_ru cols 0..127). LAYER0 -> cols j*128+f; LAYER1 -> j*256+128+f.
template <int LAYER>
__global__ void k_cheby_cand(const float* __restrict__ S) {
    __shared__ float4 s4[NNODE][32];
    __shared__ float sS[361], sS2[361];
    const int b = blockIdx.x, tid = threadIdx.x;
    __nv_bfloat16* Xh = LAYER ? g_X1h : g_X0h;
    __nv_bfloat16* Xl = LAYER ? g_X1l : g_X0l;
    constexpr int STR  = LAYER ? KP1 : KP0;
    constexpr int JSTR = LAYER ? 256 : 128;
    constexpr int COFS = LAYER ? 128 : 0;

    load_S(S, sS, sS2, tid);
    for (int i = tid; i < NNODE * 32; i += 256) {
        int n = i >> 5, f4 = i & 31;
        s4[n][f4] = *(const float4*)(g_ru + (size_t)(b * NNODE + n) * 256 + 4 * f4);
    }
    __syncthreads();

    for (int p = tid; p < NNODE * 32; p += 256) {
        int m = p >> 5, f4 = p & 31;
        float4 x0 = s4[m][f4];
        float4 a1 = make_float4(0, 0, 0, 0), a2 = make_float4(0, 0, 0, 0);
#pragma unroll
        for (int n = 0; n < NNODE; n++) {
            float4 v = s4[n][f4];
            float w1 = sS[m * NNODE + n], w2 = sS2[m * NNODE + n];
            a1.x = fmaf(w1, v.x, a1.x); a1.y = fmaf(w1, v.y, a1.y);
            a1.z = fmaf(w1, v.z, a1.z); a1.w = fmaf(w1, v.w, a1.w);
            a2.x = fmaf(w2, v.x, a2.x); a2.y = fmaf(w2, v.y, a2.y);
            a2.z = fmaf(w2, v.z, a2.z); a2.w = fmaf(w2, v.w, a2.w);
        }
        size_t base = (size_t)(b * NNODE + m) * STR + COFS + 4 * f4;
        store4(Xh, Xl, base,            x0);
        store4(Xh, Xl, base + JSTR,     a1);
        store4(Xh, Xl, base + 2 * JSTR, a2);
    }
}

// ---------------- bf16 mma.sync GEMM, BM=64 BN=128 BK=32 ---------------------
#define STAGEB 24576   // Ah 4K | Al 4K | Bh 8K | Bl 8K

template <int MODE, int LAYER, bool PROJ>
__global__ void __launch_bounds__(128, 4)
k_gemm(const float* __restrict__ bias, const float* __restrict__ Wp,
       const float* __restrict__ bp, float* __restrict__ outp) {
    constexpr int KP = LAYER ? KP1 : KP0;
    constexpr int NT = KP / 32;

    extern __shared__ __align__(16) char smem[];
    const uint32_t sbase = smem_u32(smem);

    const int tid = threadIdx.x, wid = tid >> 5, lane = tid & 31;
    const int row0 = blockIdx.x * 64;
    const int col0 = blockIdx.y * 128;
    const int wm = (wid & 1) * 32, wn = (wid >> 1) * 64;
    const int gr = lane >> 2, gc = lane & 3;

    const __nv_bfloat16* Xh = LAYER ? g_X1h : g_X0h;
    const __nv_bfloat16* Xl = LAYER ? g_X1l : g_X0l;
    const int woff = (MODE == 0) ? (LAYER ? WO_G1 : WO_G0) : (LAYER ? WO_C1 : WO_C0);
    const __nv_bfloat16* Wh = g_Wh + woff;
    const __nv_bfloat16* Wl = g_Wl + woff;

    auto load_stage = [&](int kt, int s) {
        const uint32_t stg = sbase + s * STAGEB;
#pragma unroll
        for (int i = 0; i < 12; i++) {
            int slot = tid + i * 128;
            uint32_t dst;
            const __nv_bfloat16* src;
            if (slot < 512) {
                int pl = slot >> 8, e = slot & 255;
                int r = e >> 2, c16 = e & 3;
                dst = stg + pl * 4096u + swz64(r * 64 + c16 * 16);
                src = (pl ? Xl : Xh) + (size_t)(row0 + r) * KP + kt * 32 + c16 * 8;
            } else {
                int t2 = slot - 512;
                int pl = t2 >> 9, e = t2 & 511;
                int r = e >> 2, c16 = e & 3;
                dst = stg + 8192u + pl * 8192u + swz64(r * 64 + c16 * 16);
                src = (pl ? Wl : Wh) + (size_t)(col0 + r) * KP + kt * 32 + c16 * 8;
            }
            cpasync16(dst, src);
        }
        CP_COMMIT();
    };

    float acc[2][8][4];
#pragma unroll
    for (int i = 0; i < 2; i++)
#pragma unroll
        for (int j = 0; j < 8; j++)
#pragma unroll
            for (int q = 0; q < 4; q++) acc[i][j][q] = 0.f;

    load_stage(0, 0);

    const int a_r = lane & 15, a_k = (lane >> 4) * 8;
    const int b_r = (lane & 7) + ((lane >> 4) << 3), b_k = ((lane >> 3) & 1) * 8;

    for (int kt = 0; kt < NT; kt++) {
        const int s = kt & 1;
        if (kt + 1 < NT) load_stage(kt + 1, s ^ 1);
        if (kt + 1 < NT) { CP_WAIT(1); } else { CP_WAIT(0); }
        __syncthreads();

        const uint32_t stg = sbase + s * STAGEB;
        const uint32_t sAh = stg, sAl = stg + 4096;
        const uint32_t sBh = stg + 8192, sBl = stg + 16384;

#pragma unroll
        for (int ks = 0; ks < 32; ks += 16) {
            uint32_t ah[2][4], al[2][4];
#pragma unroll
            for (int mi = 0; mi < 2; mi++) {
                uint32_t off = swz64((uint32_t)((wm + mi * 16 + a_r) * 64 + (ks + a_k) * 2));
                ldsm_x4(ah[mi], sAh + off);
                ldsm_x4(al[mi], sAl + off);
            }
#pragma unroll
            for (int nq = 0; nq < 4; nq++) {
                uint32_t bh[4], bl[4];
                uint32_t off = swz64((uint32_t)((wn + nq * 16 + b_r) * 64 + (ks + b_k) * 2));
                ldsm_x4(bh, sBh + off);
                ldsm_x4(bl, sBl + off);
#pragma unroll
                for (int half = 0; half < 2; half++) {
                    int ni = nq * 2 + half;
                    const uint32_t* pbh = &bh[half * 2];
                    const uint32_t* pbl = &bl[half * 2];
#pragma unroll
                    for (int mi = 0; mi < 2; mi++) {
                        mma_bf16(acc[mi][ni], ah[mi], pbh);
                        mma_bf16(acc[mi][ni], al[mi], pbh);
                        mma_bf16(acc[mi][ni], ah[mi], pbl);
                    }
                }
            }
        }
        __syncthreads();
    }

    // ---------------- epilogue ----------------
    float* hbuf = LAYER ? g_h1 : g_h0;
    float* red = (float*)smem;
    float pr[2] = {0.f, 0.f};
    if (PROJ) {
        if (tid < 64) red[tid] = 0.f;
        __syncthreads();
    }
#pragma unroll
    for (int mi = 0; mi < 2; mi++) {
#pragma unroll
        for (int ni = 0; ni < 8; ni++) {
            int r0 = row0 + wm + mi * 16 + gr;
            int c  = col0 + wn + ni * 8 + gc * 2;
            float b0 = bias[c], b1 = bias[c + 1];
            float* pa = acc[mi][ni];
            if (MODE == 0) {
#pragma unroll
                for (int rr = 0; rr < 2; rr++) {
                    int r = r0 + rr * 8;
                    float2 v;
                    v.x = fast_sig(pa[rr * 2 + 0] + b0);
                    v.y = fast_sig(pa[rr * 2 + 1] + b1);
                    if (col0 == 0) {
                        float2 h = *(const float2*)(&hbuf[(size_t)r * HID + c]);
                        v.x *= h.x; v.y *= h.y;
                    }
                    *(float2*)(&g_ru[(size_t)r * 256 + c]) = v;
                }
            } else {
#pragma unroll
                for (int rr = 0; rr < 2; rr++) {
                    int r = r0 + rr * 8;
                    float2 u = *(const float2*)(&g_ru[(size_t)r * 256 + 128 + c]);
                    float2 h = *(const float2*)(&hbuf[(size_t)r * HID + c]);
                    float2 o;
                    o.x = u.x * h.x + (1.f - u.x) * fast_tanh(pa[rr * 2 + 0] + b0);
                    o.y = u.y * h.y + (1.f - u.y) * fast_tanh(pa[rr * 2 + 1] + b1);
                    *(float2*)(&hbuf[(size_t)r * HID + c]) = o;
                    if (PROJ)
                        pr[rr] += o.x * Wp[c] + o.y * Wp[c + 1];
                }
            }
            if (MODE == 1 && PROJ && ni == 7) {
#pragma unroll
                for (int rr = 0; rr < 2; rr++) {
                    atomicAdd(&red[wm + mi * 16 + gr + rr * 8], pr[rr]);
                    pr[rr] = 0.f;
                }
            }
        }
    }
    if (PROJ) {
        __syncthreads();
        if (tid < 64) outp[row0 + tid] = red[tid] + bp[0];
    }
}

// ---------------- launch -----------------------------------------------------
extern "C" void kernel_launch(void* const* d_in, const int* in_sizes, int n_in,
                              void* d_out, int out_size) {
    (void)in_sizes; (void)n_in; (void)out_size;
    const float* ih  = (const float*)d_in[1];
    const float* S   = (const float*)d_in[2];
    const float* Wg0 = (const float*)d_in[3];
    const float* bg0 = (const float*)d_in[4];
    const float* Wc0 = (const float*)d_in[5];
    const float* bc0 = (const float*)d_in[6];
    const float* Wg1 = (const float*)d_in[7];
    const float* bg1 = (const float*)d_in[8];
    const float* Wc1 = (const float*)d_in[9];
    const float* bc1 = (const float*)d_in[10];
    const float* Wp  = (const float*)d_in[11];
    const float* bp  = (const float*)d_in[12];
    float* out = (float*)d_out;

    const int SMEM = 2 * STAGEB;   // 49152 B -> 4 CTAs/SM
    cudaFuncSetAttribute((const void*)k_gemm<0, 0, false>, cudaFuncAttributeMaxDynamicSharedMemorySize, SMEM);
    cudaFuncSetAttribute((const void*)k_gemm<0, 1, false>, cudaFuncAttributeMaxDynamicSharedMemorySize, SMEM);
    cudaFuncSetAttribute((const void*)k_gemm<1, 0, false>, cudaFuncAttributeMaxDynamicSharedMemorySize, SMEM);
    cudaFuncSetAttribute((const void*)k_gemm<1, 1, true>,  cudaFuncAttributeMaxDynamicSharedMemorySize, SMEM);

    k_init<<<NB_INIT, 256>>>(ih, Wg0, Wc0, Wg1, Wc1);

    for (int t = 0; t < SEQLEN; t++) {
        const float* xprev = t ? out + (size_t)(t - 1) * ROWS : nullptr;
        float* out_t = out + (size_t)t * ROWS;

        k_cheby0_gate<<<BATCH, 256>>>(S, xprev);
        k_gemm<0, 0, false><<<dim3(304, 2), 128, SMEM>>>(bg0, nullptr, nullptr, nullptr);
        k_cheby_cand<0><<<BATCH, 256>>>(S);
        k_gemm<1, 0, false><<<dim3(304, 1), 128, SMEM>>>(bc0, nullptr, nullptr, nullptr);

        k_cheby1_gate<<<BATCH, 256>>>(S);
        k_gemm<0, 1, false><<<dim3(304, 2), 128, SMEM>>>(bg1, nullptr, nullptr, nullptr);
        k_cheby_cand<1><<<BATCH, 256>>>(S);
        k_gemm<1, 1, true><<<dim3(304, 1), 128, SMEM>>>(bc1, Wp, bp, out_t);
    }
}

// round 14
// speedup vs baseline: 1.0585x; 1.0585x over previous
#include <cuda_runtime.h>
#include <cuda_bf16.h>
#include <math.h>
#include <stdint.h>

// DCGRU decoder: SEQ=32, B=1024, N=19, H=128, OUT=1, K=2 Chebyshev, 2 layers.
// R14: float2 cheby with 2 batches/block + precomputed S2 (fixes R8 regression),
//      keeps fast-math epilogue + fused init + bf16 3-pass mma.sync GEMM.

#define BATCH 1024
#define NNODE 19
#define HID   128
#define ROWS  (BATCH * NNODE)   // 19456 = 304 * 64
#define SEQLEN 32

#define KP0 416                  // layer0 K: [h*3 (384) | x0 x1 x2 | pad]
#define K0R 387
#define KP1 768

#define WO_G0 0
#define WO_C0 (WO_G0 + 256 * KP0)
#define WO_G1 (WO_C0 + 128 * KP0)
#define WO_C1 (WO_G1 + 256 * KP1)
#define WTOT  (WO_C1 + 128 * KP1)

// ---------------- persistent device scratch ---------------------------------
__device__ float g_h0[ROWS * HID];
__device__ float g_h1[ROWS * HID];
__device__ float g_ru[ROWS * 256];          // [r*h | u]
__device__ float g_S2[NNODE * NNODE];       // 2*S@S - I
__device__ __align__(16) __nv_bfloat16 g_X0h[ROWS * KP0];
__device__ __align__(16) __nv_bfloat16 g_X0l[ROWS * KP0];
__device__ __align__(16) __nv_bfloat16 g_X1h[ROWS * KP1];
__device__ __align__(16) __nv_bfloat16 g_X1l[ROWS * KP1];
__device__ __align__(16) __nv_bfloat16 g_Wh[WTOT];
__device__ __align__(16) __nv_bfloat16 g_Wl[WTOT];

// ---------------- helpers ----------------------------------------------------
__device__ __forceinline__ uint32_t smem_u32(const void* p) {
    uint32_t a;
    asm("{ .reg .u64 t; cvta.to.shared.u64 t, %1; cvt.u32.u64 %0, t; }" : "=r"(a) : "l"(p));
    return a;
}
__device__ __forceinline__ void cpasync16(uint32_t dst, const void* src) {
    asm volatile("cp.async.cg.shared.global [%0], [%1], 16;" :: "r"(dst), "l"(src) : "memory");
}
#define CP_COMMIT() asm volatile("cp.async.commit_group;" ::: "memory")
#define CP_WAIT(n)  asm volatile("cp.async.wait_group %0;" :: "n"(n) : "memory")

__device__ __forceinline__ void ldsm_x4(uint32_t* r, uint32_t addr) {
    asm volatile("ldmatrix.sync.aligned.m8n8.x4.shared.b16 {%0,%1,%2,%3}, [%4];"
                 : "=r"(r[0]), "=r"(r[1]), "=r"(r[2]), "=r"(r[3]) : "r"(addr));
}
__device__ __forceinline__ void mma_bf16(float* d, const uint32_t* a, const uint32_t* b) {
    asm volatile("mma.sync.aligned.m16n8k16.row.col.f32.bf16.bf16.f32 "
                 "{%0,%1,%2,%3},{%4,%5,%6,%7},{%8,%9},{%0,%1,%2,%3};"
                 : "+f"(d[0]), "+f"(d[1]), "+f"(d[2]), "+f"(d[3])
                 : "r"(a[0]), "r"(a[1]), "r"(a[2]), "r"(a[3]), "r"(b[0]), "r"(b[1]));
}
__device__ __forceinline__ uint32_t swz64(uint32_t o) { return o ^ ((o >> 3) & 0x30); }

__device__ __forceinline__ float fast_sig(float x) {
    return 1.f / (1.f + __expf(-x));
}
__device__ __forceinline__ float fast_tanh(float x) {
    float ax = fabsf(x);
    float t = 1.f - 2.f / (__expf(2.f * ax) + 1.f);
    return copysignf(t, x);
}

// store 2 fp32 as bf16 hi plane + bf16 residual plane (two 4B stores)
__device__ __forceinline__ void store2(__nv_bfloat16* __restrict__ H,
                                       __nv_bfloat16* __restrict__ L,
                                       size_t idx, float2 v) {
    __nv_bfloat162 h2 = __float22bfloat162_rn(v);
    *(__nv_bfloat162*)(H + idx) = h2;
    float2 hf = __bfloat1622float2(h2);
    __nv_bfloat162 l2 = __float22bfloat162_rn(make_float2(v.x - hf.x, v.y - hf.y));
    *(__nv_bfloat162*)(L + idx) = l2;
}
__device__ __forceinline__ void store1(__nv_bfloat16* H, __nv_bfloat16* L,
                                       size_t idx, float v) {
    __nv_bfloat16 h = __float2bfloat16(v);
    H[idx] = h;
    L[idx] = __float2bfloat16(v - __bfloat162float(h));
}

// ---------------- fused init: h, X0 pad, S2, all weight planes ---------------
#define NB_H    9728
#define NB_ZP   2205
#define NB_S2   2
#define NB_PG0  416
#define NB_PC0  208
#define NB_PG1  768
#define NB_PC1  384
#define NB_INIT (NB_H + NB_ZP + NB_S2 + NB_PG0 + NB_PC0 + NB_PG1 + NB_PC1)

__device__ __forceinline__ void prep_one(const float* W, int off, bool perm,
                                         int KP_, int Nw, int i) {
    if (i >= Nw * KP_) return;
    int n = i / KP_, kk = i % KP_;
    float w;
    if (perm) {
        if (kk < 384)      w = W[((kk >> 7) * 129 + 1 + (kk & 127)) * Nw + n];
        else if (kk < 387) w = W[(kk - 384) * 129 * Nw + n];
        else               w = 0.f;
    } else {
        w = (kk < 768) ? W[kk * Nw + n] : 0.f;
    }
    __nv_bfloat16 h = __float2bfloat16(w);
    g_Wh[off + i] = h;
    g_Wl[off + i] = __float2bfloat16(w - __bfloat162float(h));
}

__global__ void k_init(const float* __restrict__ ih, const float* __restrict__ S,
                       const float* __restrict__ Wg0, const float* __restrict__ Wc0,
                       const float* __restrict__ Wg1, const float* __restrict__ Wc1) {
    int blk = blockIdx.x, tid = threadIdx.x;
    if (blk < NB_H) {
        int i = blk * 256 + tid;
        if (i < ROWS * HID) { g_h0[i] = ih[i]; g_h1[i] = ih[ROWS * HID + i]; }
        return;
    }
    blk -= NB_H;
    if (blk < NB_ZP) {
        int i = blk * 256 + tid;
        const int PC = KP0 - K0R;   // 29
        if (i < ROWS * PC) {
            int row = i / PC, c = K0R + i % PC;
            g_X0h[(size_t)row * KP0 + c] = __float2bfloat16(0.f);
            g_X0l[(size_t)row * KP0 + c] = __float2bfloat16(0.f);
        }
        return;
    }
    blk -= NB_ZP;
    if (blk < NB_S2) {
        int i = blk * 256 + tid;
        if (i < NNODE * NNODE) {
            int m = i / NNODE, n = i % NNODE;
            float acc = 0.f;
#pragma unroll
            for (int k = 0; k < NNODE; k++) acc += S[m * NNODE + k] * S[k * NNODE + n];
            g_S2[i] = 2.f * acc - (m == n ? 1.f : 0.f);
        }
        return;
    }
    blk -= NB_S2;
    if (blk < NB_PG0) { prep_one(Wg0, WO_G0, true, KP0, 256, blk * 256 + tid); return; }
    blk -= NB_PG0;
    if (blk < NB_PC0) { prep_one(Wc0, WO_C0, true, KP0, 128, blk * 256 + tid); return; }
    blk -= NB_PC0;
    if (blk < NB_PG1) { prep_one(Wg1, WO_G1, false, KP1, 256, blk * 256 + tid); return; }
    blk -= NB_PG1;
    prep_one(Wc1, WO_C1, false, KP1, 128, blk * 256 + tid);
}

// ---------------- cheby kernels: 2 batches/block, float2 ---------------------
// Each 256-thread block = two 128-thread sub-blocks, one batch each.
__device__ __forceinline__ void load_SS2(const float* __restrict__ S,
                                         float* sS, float* sS2, int tid) {
    for (int i = tid; i < 361; i += 256) { sS[i] = S[i]; sS2[i] = g_S2[i]; }
}

// layer0 gate: h feats -> cols j*128+f; x feat (scalar) -> cols 384+j.
__global__ void __launch_bounds__(256)
k_cheby0_gate(const float* __restrict__ S, const float* __restrict__ xprev) {
    __shared__ float2 s2[2][NNODE][64];
    __shared__ float sx[2][NNODE];
    __shared__ float sS[361], sS2[361];
    const int tid = threadIdx.x;
    const int sub = tid >> 7, lt = tid & 127;
    const int b = blockIdx.x * 2 + sub;

    load_SS2(S, sS, sS2, tid);
    for (int i = lt; i < NNODE * 64; i += 128) {
        int n = i >> 6, f2 = i & 63;
        s2[sub][n][f2] = *(const float2*)(g_h0 + (size_t)(b * NNODE + n) * HID + 2 * f2);
    }
    if (lt < NNODE) sx[sub][lt] = xprev ? xprev[b * NNODE + lt] : 0.f;
    __syncthreads();

    for (int p = lt; p < NNODE * 64; p += 128) {
        int m = p >> 6, f2 = p & 63;
        float2 x0 = s2[sub][m][f2];
        float2 a1 = make_float2(0.f, 0.f), a2 = make_float2(0.f, 0.f);
#pragma unroll
        for (int n = 0; n < NNODE; n++) {
            float2 v = s2[sub][n][f2];
            float w1 = sS[m * NNODE + n], w2 = sS2[m * NNODE + n];
            a1.x = fmaf(w1, v.x, a1.x); a1.y = fmaf(w1, v.y, a1.y);
            a2.x = fmaf(w2, v.x, a2.x); a2.y = fmaf(w2, v.y, a2.y);
        }
        size_t base = (size_t)(b * NNODE + m) * KP0 + 2 * f2;
        store2(g_X0h, g_X0l, base,       x0);
        store2(g_X0h, g_X0l, base + 128, a1);
        store2(g_X0h, g_X0l, base + 256, a2);
    }
    if (lt < NNODE) {
        int m = lt;
        float x0 = sx[sub][m], a1 = 0.f, a2 = 0.f;
#pragma unroll
        for (int n = 0; n < NNODE; n++) {
            a1 = fmaf(sS[m * NNODE + n], sx[sub][n], a1);
            a2 = fmaf(sS2[m * NNODE + n], sx[sub][n], a2);
        }
        size_t base = (size_t)(b * NNODE + m) * KP0 + 384;
        store1(g_X0h, g_X0l, base, x0);
        store1(g_X0h, g_X0l, base + 1, a1);
        store1(g_X0h, g_X0l, base + 2, a2);
    }
}

// layer1 gate: src [h0|h1] (256 feats) -> cols j*256+f.
__global__ void __launch_bounds__(256)
k_cheby1_gate(const float* __restrict__ S) {
    __shared__ float2 s2[2][NNODE][128];
    __shared__ float sS[361], sS2[361];
    const int tid = threadIdx.x;
    const int sub = tid >> 7, lt = tid & 127;
    const int b = blockIdx.x * 2 + sub;

    load_SS2(S, sS, sS2, tid);
    for (int i = lt; i < NNODE * 128; i += 128) {
        int n = i >> 7, f2 = i & 127;
        size_t row = (size_t)(b * NNODE + n);
        s2[sub][n][f2] = (f2 < 64)
            ? *(const float2*)(g_h0 + row * HID + 2 * f2)
            : *(const float2*)(g_h1 + row * HID + 2 * (f2 - 64));
    }
    __syncthreads();

    for (int p = lt; p < NNODE * 128; p += 128) {
        int m = p >> 7, f2 = p & 127;
        float2 x0 = s2[sub][m][f2];
        float2 a1 = make_float2(0.f, 0.f), a2 = make_float2(0.f, 0.f);
#pragma unroll
        for (int n = 0; n < NNODE; n++) {
            float2 v = s2[sub][n][f2];
            float w1 = sS[m * NNODE + n], w2 = sS2[m * NNODE + n];
            a1.x = fmaf(w1, v.x, a1.x); a1.y = fmaf(w1, v.y, a1.y);
            a2.x = fmaf(w2, v.x, a2.x); a2.y = fmaf(w2, v.y, a2.y);
        }
        size_t base = (size_t)(b * NNODE + m) * KP1 + 2 * f2;
        store2(g_X1h, g_X1l, base,       x0);
        store2(g_X1h, g_X1l, base + 256, a1);
        store2(g_X1h, g_X1l, base + 512, a2);
    }
}

// cand cheby: src r*h (g_ru cols 0..127). LAYER0 -> cols j*128+f; LAYER1 -> j*256+128+f.
template <int LAYER>
__global__ void __launch_bounds__(256)
k_cheby_cand(const float* __restrict__ S) {
    __shared__ float2 s2[2][NNODE][64];
    __shared__ float sS[361], sS2[361];
    const int tid = threadIdx.x;
    const int sub = tid >> 7, lt = tid & 127;
    const int b = blockIdx.x * 2 + sub;
    __nv_bfloat16* Xh = LAYER ? g_X1h : g_X0h;
    __nv_bfloat16* Xl = LAYER ? g_X1l : g_X0l;
    constexpr int STR  = LAYER ? KP1 : KP0;
    constexpr int JSTR = LAYER ? 256 : 128;
    constexpr int COFS = LAYER ? 128 : 0;

    load_SS2(S, sS, sS2, tid);
    for (int i = lt; i < NNODE * 64; i += 128) {
        int n = i >> 6, f2 = i & 63;
        s2[sub][n][f2] = *(const float2*)(g_ru + (size_t)(b * NNODE + n) * 256 + 2 * f2);
    }
    __syncthreads();

    for (int p = lt; p < NNODE * 64; p += 128) {
        int m = p >> 6, f2 = p & 63;
        float2 x0 = s2[sub][m][f2];
        float2 a1 = make_float2(0.f, 0.f), a2 = make_float2(0.f, 0.f);
#pragma unroll
        for (int n = 0; n < NNODE; n++) {
            float2 v = s2[sub][n][f2];
            float w1 = sS[m * NNODE + n], w2 = sS2[m * NNODE + n];
            a1.x = fmaf(w1, v.x, a1.x); a1.y = fmaf(w1, v.y, a1.y);
            a2.x = fmaf(w2, v.x, a2.x); a2.y = fmaf(w2, v.y, a2.y);
        }
        size_t base = (size_t)(b * NNODE + m) * STR + COFS + 2 * f2;
        store2(Xh, Xl, base,            x0);
        store2(Xh, Xl, base + JSTR,     a1);
        store2(Xh, Xl, base + 2 * JSTR, a2);
    }
}

// ---------------- bf16 mma.sync GEMM, BM=64 BN=128 BK=32 ---------------------
#define STAGEB 24576   // Ah 4K | Al 4K | Bh 8K | Bl 8K

template <int MODE, int LAYER, bool PROJ>
__global__ void __launch_bounds__(128, 4)
k_gemm(const float* __restrict__ bias, const float* __restrict__ Wp,
       const float* __restrict__ bp, float* __restrict__ outp) {
    constexpr int KP = LAYER ? KP1 : KP0;
    constexpr int NT = KP / 32;

    extern __shared__ __align__(16) char smem[];
    const uint32_t sbase = smem_u32(smem);

    const int tid = threadIdx.x, wid = tid >> 5, lane = tid & 31;
    const int row0 = blockIdx.x * 64;
    const int col0 = blockIdx.y * 128;
    const int wm = (wid & 1) * 32, wn = (wid >> 1) * 64;
    const int gr = lane >> 2, gc = lane & 3;

    const __nv_bfloat16* Xh = LAYER ? g_X1h : g_X0h;
    const __nv_bfloat16* Xl = LAYER ? g_X1l : g_X0l;
    const int woff = (MODE == 0) ? (LAYER ? WO_G1 : WO_G0) : (LAYER ? WO_C1 : WO_C0);
    const __nv_bfloat16* Wh = g_Wh + woff;
    const __nv_bfloat16* Wl = g_Wl + woff;

    auto load_stage = [&](int kt, int s) {
        const uint32_t stg = sbase + s * STAGEB;
#pragma unroll
        for (int i = 0; i < 12; i++) {
            int slot = tid + i * 128;
            uint32_t dst;
            const __nv_bfloat16* src;
            if (slot < 512) {
                int pl = slot >> 8, e = slot & 255;
                int r = e >> 2, c16 = e & 3;
                dst = stg + pl * 4096u + swz64(r * 64 + c16 * 16);
                src = (pl ? Xl : Xh) + (size_t)(row0 + r) * KP + kt * 32 + c16 * 8;
            } else {
                int t2 = slot - 512;
                int pl = t2 >> 9, e = t2 & 511;
                int r = e >> 2, c16 = e & 3;
                dst = stg + 8192u + pl * 8192u + swz64(r * 64 + c16 * 16);
                src = (pl ? Wl : Wh) + (size_t)(col0 + r) * KP + kt * 32 + c16 * 8;
            }
            cpasync16(dst, src);
        }
        CP_COMMIT();
    };

    float acc[2][8][4];
#pragma unroll
    for (int i = 0; i < 2; i++)
#pragma unroll
        for (int j = 0; j < 8; j++)
#pragma unroll
            for (int q = 0; q < 4; q++) acc[i][j][q] = 0.f;

    load_stage(0, 0);

    const int a_r = lane & 15, a_k = (lane >> 4) * 8;
    const int b_r = (lane & 7) + ((lane >> 4) << 3), b_k = ((lane >> 3) & 1) * 8;

    for (int kt = 0; kt < NT; kt++) {
        const int s = kt & 1;
        if (kt + 1 < NT) load_stage(kt + 1, s ^ 1);
        if (kt + 1 < NT) { CP_WAIT(1); } else { CP_WAIT(0); }
        __syncthreads();

        const uint32_t stg = sbase + s * STAGEB;
        const uint32_t sAh = stg, sAl = stg + 4096;
        const uint32_t sBh = stg + 8192, sBl = stg + 16384;

#pragma unroll
        for (int ks = 0; ks < 32; ks += 16) {
            uint32_t ah[2][4], al[2][4];
#pragma unroll
            for (int mi = 0; mi < 2; mi++) {
                uint32_t off = swz64((uint32_t)((wm + mi * 16 + a_r) * 64 + (ks + a_k) * 2));
                ldsm_x4(ah[mi], sAh + off);
                ldsm_x4(al[mi], sAl + off);
            }
#pragma unroll
            for (int nq = 0; nq < 4; nq++) {
                uint32_t bh[4], bl[4];
                uint32_t off = swz64((uint32_t)((wn + nq * 16 + b_r) * 64 + (ks + b_k) * 2));
                ldsm_x4(bh, sBh + off);
                ldsm_x4(bl, sBl + off);
#pragma unroll
                for (int half = 0; half < 2; half++) {
                    int ni = nq * 2 + half;
                    const uint32_t* pbh = &bh[half * 2];
                    const uint32_t* pbl = &bl[half * 2];
#pragma unroll
                    for (int mi = 0; mi < 2; mi++) {
                        mma_bf16(acc[mi][ni], ah[mi], pbh);
                        mma_bf16(acc[mi][ni], al[mi], pbh);
                        mma_bf16(acc[mi][ni], ah[mi], pbl);
                    }
                }
            }
        }
        __syncthreads();
    }

    // ---------------- epilogue ----------------
    float* hbuf = LAYER ? g_h1 : g_h0;
    float* red = (float*)smem;
    float pr[2] = {0.f, 0.f};
    if (PROJ) {
        if (tid < 64) red[tid] = 0.f;
        __syncthreads();
    }
#pragma unroll
    for (int mi = 0; mi < 2; mi++) {
#pragma unroll
        for (int ni = 0; ni < 8; ni++) {
            int r0 = row0 + wm + mi * 16 + gr;
            int c  = col0 + wn + ni * 8 + gc * 2;
            float b0 = bias[c], b1 = bias[c + 1];
            float* pa = acc[mi][ni];
            if (MODE == 0) {
#pragma unroll
                for (int rr = 0; rr < 2; rr++) {
                    int r = r0 + rr * 8;
                    float2 v;
                    v.x = fast_sig(pa[rr * 2 + 0] + b0);
                    v.y = fast_sig(pa[rr * 2 + 1] + b1);
                    if (col0 == 0) {
                        float2 h = *(const float2*)(&hbuf[(size_t)r * HID + c]);
                        v.x *= h.x; v.y *= h.y;
                    }
                    *(float2*)(&g_ru[(size_t)r * 256 + c]) = v;
                }
            } else {
#pragma unroll
                for (int rr = 0; rr < 2; rr++) {
                    int r = r0 + rr * 8;
                    float2 u = *(const float2*)(&g_ru[(size_t)r * 256 + 128 + c]);
                    float2 h = *(const float2*)(&hbuf[(size_t)r * HID + c]);
                    float2 o;
                    o.x = u.x * h.x + (1.f - u.x) * fast_tanh(pa[rr * 2 + 0] + b0);
                    o.y = u.y * h.y + (1.f - u.y) * fast_tanh(pa[rr * 2 + 1] + b1);
                    *(float2*)(&hbuf[(size_t)r * HID + c]) = o;
                    if (PROJ)
                        pr[rr] += o.x * Wp[c] + o.y * Wp[c + 1];
                }
            }
            if (MODE == 1 && PROJ && ni == 7) {
#pragma unroll
                for (int rr = 0; rr < 2; rr++) {
                    atomicAdd(&red[wm + mi * 16 + gr + rr * 8], pr[rr]);
                    pr[rr] = 0.f;
                }
            }
        }
    }
    if (PROJ) {
        __syncthreads();
        if (tid < 64) outp[row0 + tid] = red[tid] + bp[0];
    }
}

// ---------------- launch -----------------------------------------------------
extern "C" void kernel_launch(void* const* d_in, const int* in_sizes, int n_in,
                              void* d_out, int out_size) {
    (void)in_sizes; (void)n_in; (void)out_size;
    const float* ih  = (const float*)d_in[1];
    const float* S   = (const float*)d_in[2];
    const float* Wg0 = (const float*)d_in[3];
    const float* bg0 = (const float*)d_in[4];
    const float* Wc0 = (const float*)d_in[5];
    const float* bc0 = (const float*)d_in[6];
    const float* Wg1 = (const float*)d_in[7];
    const float* bg1 = (const float*)d_in[8];
    const float* Wc1 = (const float*)d_in[9];
    const float* bc1 = (const float*)d_in[10];
    const float* Wp  = (const float*)d_in[11];
    const float* bp  = (const float*)d_in[12];
    float* out = (float*)d_out;

    const int SMEM = 2 * STAGEB;   // 49152 B -> 4 CTAs/SM
    cudaFuncSetAttribute((const void*)k_gemm<0, 0, false>, cudaFuncAttributeMaxDynamicSharedMemorySize, SMEM);
    cudaFuncSetAttribute((const void*)k_gemm<0, 1, false>, cudaFuncAttributeMaxDynamicSharedMemorySize, SMEM);
    cudaFuncSetAttribute((const void*)k_gemm<1, 0, false>, cudaFuncAttributeMaxDynamicSharedMemorySize, SMEM);
    cudaFuncSetAttribute((const void*)k_gemm<1, 1, true>,  cudaFuncAttributeMaxDynamicSharedMemorySize, SMEM);

    k_init<<<NB_INIT, 256>>>(ih, S, Wg0, Wc0, Wg1, Wc1);

    for (int t = 0; t < SEQLEN; t++) {
        const float* xprev = t ? out + (size_t)(t - 1) * ROWS : nullptr;
        float* out_t = out + (size_t)t * ROWS;

        k_cheby0_gate<<<BATCH / 2, 256>>>(S, xprev);
        k_gemm<0, 0, false><<<dim3(304, 2), 128, SMEM>>>(bg0, nullptr, nullptr, nullptr);
        k_cheby_cand<0><<<BATCH / 2, 256>>>(S);
        k_gemm<1, 0, false><<<dim3(304, 1), 128, SMEM>>>(bc0, nullptr, nullptr, nullptr);

        k_cheby1_gate<<<BATCH / 2, 256>>>(S);
        k_gemm<0, 1, false><<<dim3(304, 2), 128, SMEM>>>(bg1, nullptr, nullptr, nullptr);
        k_cheby_cand<1><<<BATCH / 2, 256>>>(S);
        k_gemm<1, 1, true><<<dim3(304, 1), 128, SMEM>>>(bc1, Wp, bp, out_t);
    }
}

// round 16
// speedup vs baseline: 1.2460x; 1.1772x over previous
#include <cuda_runtime.h>
#include <cuda_fp16.h>
#include <math.h>
#include <stdint.h>

// DCGRU decoder: SEQ=32, B=1024, N=19, H=128, OUT=1, K=2 Chebyshev, 2 layers.
// R15: fp16 2-pass split GEMM (A=hi+lo corrected, W single fp16 plane).
//      Predicted rel_err ~1.5e-4 (vs 1e-3 threshold). Cheby/init as R14.

#define BATCH 1024
#define NNODE 19
#define HID   128
#define ROWS  (BATCH * NNODE)   // 19456 = 304 * 64
#define SEQLEN 32

#define KP0 416                  // layer0 K: [h*3 (384) | x0 x1 x2 | pad]
#define K0R 387
#define KP1 768

#define WO_G0 0
#define WO_C0 (WO_G0 + 256 * KP0)
#define WO_G1 (WO_C0 + 128 * KP0)
#define WO_C1 (WO_G1 + 256 * KP1)
#define WTOT  (WO_C1 + 128 * KP1)

// ---------------- persistent device scratch ---------------------------------
__device__ float g_h0[ROWS * HID];
__device__ float g_h1[ROWS * HID];
__device__ float g_ru[ROWS * 256];          // [r*h | u]
__device__ float g_S2[NNODE * NNODE];       // 2*S@S - I
__device__ __align__(16) __half g_X0h[ROWS * KP0];
__device__ __align__(16) __half g_X0l[ROWS * KP0];
__device__ __align__(16) __half g_X1h[ROWS * KP1];
__device__ __align__(16) __half g_X1l[ROWS * KP1];
__device__ __align__(16) __half g_Wf[WTOT];

// ---------------- helpers ----------------------------------------------------
__device__ __forceinline__ uint32_t smem_u32(const void* p) {
    uint32_t a;
    asm("{ .reg .u64 t; cvta.to.shared.u64 t, %1; cvt.u32.u64 %0, t; }" : "=r"(a) : "l"(p));
    return a;
}
__device__ __forceinline__ void cpasync16(uint32_t dst, const void* src) {
    asm volatile("cp.async.cg.shared.global [%0], [%1], 16;" :: "r"(dst), "l"(src) : "memory");
}
#define CP_COMMIT() asm volatile("cp.async.commit_group;" ::: "memory")
#define CP_WAIT(n)  asm volatile("cp.async.wait_group %0;" :: "n"(n) : "memory")

__device__ __forceinline__ void ldsm_x4(uint32_t* r, uint32_t addr) {
    asm volatile("ldmatrix.sync.aligned.m8n8.x4.shared.b16 {%0,%1,%2,%3}, [%4];"
                 : "=r"(r[0]), "=r"(r[1]), "=r"(r[2]), "=r"(r[3]) : "r"(addr));
}
__device__ __forceinline__ void mma_f16(float* d, const uint32_t* a, const uint32_t* b) {
    asm volatile("mma.sync.aligned.m16n8k16.row.col.f32.f16.f16.f32 "
                 "{%0,%1,%2,%3},{%4,%5,%6,%7},{%8,%9},{%0,%1,%2,%3};"
                 : "+f"(d[0]), "+f"(d[1]), "+f"(d[2]), "+f"(d[3])
                 : "r"(a[0]), "r"(a[1]), "r"(a[2]), "r"(a[3]), "r"(b[0]), "r"(b[1]));
}
__device__ __forceinline__ uint32_t swz64(uint32_t o) { return o ^ ((o >> 3) & 0x30); }

__device__ __forceinline__ float fast_sig(float x) {
    return 1.f / (1.f + __expf(-x));
}
__device__ __forceinline__ float fast_tanh(float x) {
    float ax = fabsf(x);
    float t = 1.f - 2.f / (__expf(2.f * ax) + 1.f);
    return copysignf(t, x);
}

// store 2 fp32 as fp16 hi plane + fp16 residual plane (two 4B stores)
__device__ __forceinline__ void store2(__half* __restrict__ H, __half* __restrict__ L,
                                       size_t idx, float2 v) {
    __half2 h2 = __float22half2_rn(v);
    *(__half2*)(H + idx) = h2;
    float2 hf = __half22float2(h2);
    __half2 l2 = __float22half2_rn(make_float2(v.x - hf.x, v.y - hf.y));
    *(__half2*)(L + idx) = l2;
}
__device__ __forceinline__ void store1(__half* H, __half* L, size_t idx, float v) {
    __half h = __float2half_rn(v);
    H[idx] = h;
    L[idx] = __float2half_rn(v - __half2float(h));
}

// ---------------- fused init: h, X0 pad, S2, weight plane --------------------
#define NB_H    9728
#define NB_ZP   2205
#define NB_S2   2
#define NB_PG0  416
#define NB_PC0  208
#define NB_PG1  768
#define NB_PC1  384
#define NB_INIT (NB_H + NB_ZP + NB_S2 + NB_PG0 + NB_PC0 + NB_PG1 + NB_PC1)

__device__ __forceinline__ void prep_one(const float* W, int off, bool perm,
                                         int KP_, int Nw, int i) {
    if (i >= Nw * KP_) return;
    int n = i / KP_, kk = i % KP_;
    float w;
    if (perm) {
        if (kk < 384)      w = W[((kk >> 7) * 129 + 1 + (kk & 127)) * Nw + n];
        else if (kk < 387) w = W[(kk - 384) * 129 * Nw + n];
        else               w = 0.f;
    } else {
        w = (kk < 768) ? W[kk * Nw + n] : 0.f;
    }
    g_Wf[off + i] = __float2half_rn(w);
}

__global__ void k_init(const float* __restrict__ ih, const float* __restrict__ S,
                       const float* __restrict__ Wg0, const float* __restrict__ Wc0,
                       const float* __restrict__ Wg1, const float* __restrict__ Wc1) {
    int blk = blockIdx.x, tid = threadIdx.x;
    if (blk < NB_H) {
        int i = blk * 256 + tid;
        if (i < ROWS * HID) { g_h0[i] = ih[i]; g_h1[i] = ih[ROWS * HID + i]; }
        return;
    }
    blk -= NB_H;
    if (blk < NB_ZP) {
        int i = blk * 256 + tid;
        const int PC = KP0 - K0R;   // 29
        if (i < ROWS * PC) {
            int row = i / PC, c = K0R + i % PC;
            g_X0h[(size_t)row * KP0 + c] = __float2half_rn(0.f);
            g_X0l[(size_t)row * KP0 + c] = __float2half_rn(0.f);
        }
        return;
    }
    blk -= NB_ZP;
    if (blk < NB_S2) {
        int i = blk * 256 + tid;
        if (i < NNODE * NNODE) {
            int m = i / NNODE, n = i % NNODE;
            float acc = 0.f;
#pragma unroll
            for (int k = 0; k < NNODE; k++) acc += S[m * NNODE + k] * S[k * NNODE + n];
            g_S2[i] = 2.f * acc - (m == n ? 1.f : 0.f);
        }
        return;
    }
    blk -= NB_S2;
    if (blk < NB_PG0) { prep_one(Wg0, WO_G0, true, KP0, 256, blk * 256 + tid); return; }
    blk -= NB_PG0;
    if (blk < NB_PC0) { prep_one(Wc0, WO_C0, true, KP0, 128, blk * 256 + tid); return; }
    blk -= NB_PC0;
    if (blk < NB_PG1) { prep_one(Wg1, WO_G1, false, KP1, 256, blk * 256 + tid); return; }
    blk -= NB_PG1;
    prep_one(Wc1, WO_C1, false, KP1, 128, blk * 256 + tid);
}

// ---------------- cheby kernels: 2 batches/block, float2 ---------------------
__device__ __forceinline__ void load_SS2(const float* __restrict__ S,
                                         float* sS, float* sS2, int tid) {
    for (int i = tid; i < 361; i += 256) { sS[i] = S[i]; sS2[i] = g_S2[i]; }
}

// layer0 gate: h feats -> cols j*128+f; x feat (scalar) -> cols 384+j.
__global__ void __launch_bounds__(256)
k_cheby0_gate(const float* __restrict__ S, const float* __restrict__ xprev) {
    __shared__ float2 s2[2][NNODE][64];
    __shared__ float sx[2][NNODE];
    __shared__ float sS[361], sS2[361];
    const int tid = threadIdx.x;
    const int sub = tid >> 7, lt = tid & 127;
    const int b = blockIdx.x * 2 + sub;

    load_SS2(S, sS, sS2, tid);
    for (int i = lt; i < NNODE * 64; i += 128) {
        int n = i >> 6, f2 = i & 63;
        s2[sub][n][f2] = *(const float2*)(g_h0 + (size_t)(b * NNODE + n) * HID + 2 * f2);
    }
    if (lt < NNODE) sx[sub][lt] = xprev ? xprev[b * NNODE + lt] : 0.f;
    __syncthreads();

    for (int p = lt; p < NNODE * 64; p += 128) {
        int m = p >> 6, f2 = p & 63;
        float2 x0 = s2[sub][m][f2];
        float2 a1 = make_float2(0.f, 0.f), a2 = make_float2(0.f, 0.f);
#pragma unroll
        for (int n = 0; n < NNODE; n++) {
            float2 v = s2[sub][n][f2];
            float w1 = sS[m * NNODE + n], w2 = sS2[m * NNODE + n];
            a1.x = fmaf(w1, v.x, a1.x); a1.y = fmaf(w1, v.y, a1.y);
            a2.x = fmaf(w2, v.x, a2.x); a2.y = fmaf(w2, v.y, a2.y);
        }
        size_t base = (size_t)(b * NNODE + m) * KP0 + 2 * f2;
        store2(g_X0h, g_X0l, base,       x0);
        store2(g_X0h, g_X0l, base + 128, a1);
        store2(g_X0h, g_X0l, base + 256, a2);
    }
    if (lt < NNODE) {
        int m = lt;
        float x0 = sx[sub][m], a1 = 0.f, a2 = 0.f;
#pragma unroll
        for (int n = 0; n < NNODE; n++) {
            a1 = fmaf(sS[m * NNODE + n], sx[sub][n], a1);
            a2 = fmaf(sS2[m * NNODE + n], sx[sub][n], a2);
        }
        size_t base = (size_t)(b * NNODE + m) * KP0 + 384;
        store1(g_X0h, g_X0l, base, x0);
        store1(g_X0h, g_X0l, base + 1, a1);
        store1(g_X0h, g_X0l, base + 2, a2);
    }
}

// layer1 gate: src [h0|h1] (256 feats) -> cols j*256+f.
__global__ void __launch_bounds__(256)
k_cheby1_gate(const float* __restrict__ S) {
    __shared__ float2 s2[2][NNODE][128];
    __shared__ float sS[361], sS2[361];
    const int tid = threadIdx.x;
    const int sub = tid >> 7, lt = tid & 127;
    const int b = blockIdx.x * 2 + sub;

    load_SS2(S, sS, sS2, tid);
    for (int i = lt; i < NNODE * 128; i += 128) {
        int n = i >> 7, f2 = i & 127;
        size_t row = (size_t)(b * NNODE + n);
        s2[sub][n][f2] = (f2 < 64)
            ? *(const float2*)(g_h0 + row * HID + 2 * f2)
            : *(const float2*)(g_h1 + row * HID + 2 * (f2 - 64));
    }
    __syncthreads();

    for (int p = lt; p < NNODE * 128; p += 128) {
        int m = p >> 7, f2 = p & 127;
        float2 x0 = s2[sub][m][f2];
        float2 a1 = make_float2(0.f, 0.f), a2 = make_float2(0.f, 0.f);
#pragma unroll
        for (int n = 0; n < NNODE; n++) {
            float2 v = s2[sub][n][f2];
            float w1 = sS[m * NNODE + n], w2 = sS2[m * NNODE + n];
            a1.x = fmaf(w1, v.x, a1.x); a1.y = fmaf(w1, v.y, a1.y);
            a2.x = fmaf(w2, v.x, a2.x); a2.y = fmaf(w2, v.y, a2.y);
        }
        size_t base = (size_t)(b * NNODE + m) * KP1 + 2 * f2;
        store2(g_X1h, g_X1l, base,       x0);
        store2(g_X1h, g_X1l, base + 256, a1);
        store2(g_X1h, g_X1l, base + 512, a2);
    }
}

// cand cheby: src r*h (g_ru cols 0..127). LAYER0 -> cols j*128+f; LAYER1 -> j*256+128+f.
template <int LAYER>
__global__ void __launch_bounds__(256)
k_cheby_cand(const float* __restrict__ S) {
    __shared__ float2 s2[2][NNODE][64];
    __shared__ float sS[361], sS2[361];
    const int tid = threadIdx.x;
    const int sub = tid >> 7, lt = tid & 127;
    const int b = blockIdx.x * 2 + sub;
    __half* Xh = LAYER ? g_X1h : g_X0h;
    __half* Xl = LAYER ? g_X1l : g_X0l;
    constexpr int STR  = LAYER ? KP1 : KP0;
    constexpr int JSTR = LAYER ? 256 : 128;
    constexpr int COFS = LAYER ? 128 : 0;

    load_SS2(S, sS, sS2, tid);
    for (int i = lt; i < NNODE * 64; i += 128) {
        int n = i >> 6, f2 = i & 63;
        s2[sub][n][f2] = *(const float2*)(g_ru + (size_t)(b * NNODE + n) * 256 + 2 * f2);
    }
    __syncthreads();

    for (int p = lt; p < NNODE * 64; p += 128) {
        int m = p >> 6, f2 = p & 63;
        float2 x0 = s2[sub][m][f2];
        float2 a1 = make_float2(0.f, 0.f), a2 = make_float2(0.f, 0.f);
#pragma unroll
        for (int n = 0; n < NNODE; n++) {
            float2 v = s2[sub][n][f2];
            float w1 = sS[m * NNODE + n], w2 = sS2[m * NNODE + n];
            a1.x = fmaf(w1, v.x, a1.x); a1.y = fmaf(w1, v.y, a1.y);
            a2.x = fmaf(w2, v.x, a2.x); a2.y = fmaf(w2, v.y, a2.y);
        }
        size_t base = (size_t)(b * NNODE + m) * STR + COFS + 2 * f2;
        store2(Xh, Xl, base,            x0);
        store2(Xh, Xl, base + JSTR,     a1);
        store2(Xh, Xl, base + 2 * JSTR, a2);
    }
}

// ---------------- fp16 2-pass mma.sync GEMM, BM=64 BN=128 BK=32 --------------
#define STAGEB 16384   // Ah 4K | Al 4K | B 8K

template <int MODE, int LAYER, bool PROJ>
__global__ void __launch_bounds__(128, 4)
k_gemm(const float* __restrict__ bias, const float* __restrict__ Wp,
       const float* __restrict__ bp, float* __restrict__ outp) {
    constexpr int KP = LAYER ? KP1 : KP0;
    constexpr int NT = KP / 32;

    extern __shared__ __align__(16) char smem[];
    const uint32_t sbase = smem_u32(smem);

    const int tid = threadIdx.x, wid = tid >> 5, lane = tid & 31;
    const int row0 = blockIdx.x * 64;
    const int col0 = blockIdx.y * 128;
    const int wm = (wid & 1) * 32, wn = (wid >> 1) * 64;
    const int gr = lane >> 2, gc = lane & 3;

    const __half* Xh = LAYER ? g_X1h : g_X0h;
    const __half* Xl = LAYER ? g_X1l : g_X0l;
    const int woff = (MODE == 0) ? (LAYER ? WO_G1 : WO_G0) : (LAYER ? WO_C1 : WO_C0);
    const __half* W = g_Wf + woff;

    auto load_stage = [&](int kt, int s) {
        const uint32_t stg = sbase + s * STAGEB;
#pragma unroll
        for (int i = 0; i < 8; i++) {
            int slot = tid + i * 128;            // 0..1023
            uint32_t dst;
            const __half* src;
            if (slot < 512) {                    // A planes: 2 x (64 rows x 4 chunks)
                int pl = slot >> 8, e = slot & 255;
                int r = e >> 2, c16 = e & 3;
                dst = stg + pl * 4096u + swz64(r * 64 + c16 * 16);
                src = (pl ? Xl : Xh) + (size_t)(row0 + r) * KP + kt * 32 + c16 * 8;
            } else {                             // B plane: 128 rows x 4 chunks
                int e = slot - 512;
                int r = e >> 2, c16 = e & 3;
                dst = stg + 8192u + swz64(r * 64 + c16 * 16);
                src = W + (size_t)(col0 + r) * KP + kt * 32 + c16 * 8;
            }
            cpasync16(dst, src);
        }
        CP_COMMIT();
    };

    float acc[2][8][4];
#pragma unroll
    for (int i = 0; i < 2; i++)
#pragma unroll
        for (int j = 0; j < 8; j++)
#pragma unroll
            for (int q = 0; q < 4; q++) acc[i][j][q] = 0.f;

    load_stage(0, 0);

    const int a_r = lane & 15, a_k = (lane >> 4) * 8;
    const int b_r = (lane & 7) + ((lane >> 4) << 3), b_k = ((lane >> 3) & 1) * 8;

    for (int kt = 0; kt < NT; kt++) {
        const int s = kt & 1;
        if (kt + 1 < NT) load_stage(kt + 1, s ^ 1);
        if (kt + 1 < NT) { CP_WAIT(1); } else { CP_WAIT(0); }
        __syncthreads();

        const uint32_t stg = sbase + s * STAGEB;
        const uint32_t sAh = stg, sAl = stg + 4096;
        const uint32_t sB  = stg + 8192;

#pragma unroll
        for (int ks = 0; ks < 32; ks += 16) {
            uint32_t ah[2][4], al[2][4];
#pragma unroll
            for (int mi = 0; mi < 2; mi++) {
                uint32_t off = swz64((uint32_t)((wm + mi * 16 + a_r) * 64 + (ks + a_k) * 2));
                ldsm_x4(ah[mi], sAh + off);
                ldsm_x4(al[mi], sAl + off);
            }
#pragma unroll
            for (int nq = 0; nq < 4; nq++) {
                uint32_t bb[4];
                uint32_t off = swz64((uint32_t)((wn + nq * 16 + b_r) * 64 + (ks + b_k) * 2));
                ldsm_x4(bb, sB + off);
#pragma unroll
                for (int half = 0; half < 2; half++) {
                    int ni = nq * 2 + half;
                    const uint32_t* pb = &bb[half * 2];
#pragma unroll
                    for (int mi = 0; mi < 2; mi++) {
                        mma_f16(acc[mi][ni], ah[mi], pb);
                        mma_f16(acc[mi][ni], al[mi], pb);
                    }
                }
            }
        }
        __syncthreads();
    }

    // ---------------- epilogue ----------------
    float* hbuf = LAYER ? g_h1 : g_h0;
    float* red = (float*)smem;
    float pr[2] = {0.f, 0.f};
    if (PROJ) {
        if (tid < 64) red[tid] = 0.f;
        __syncthreads();
    }
#pragma unroll
    for (int mi = 0; mi < 2; mi++) {
#pragma unroll
        for (int ni = 0; ni < 8; ni++) {
            int r0 = row0 + wm + mi * 16 + gr;
            int c  = col0 + wn + ni * 8 + gc * 2;
            float b0 = bias[c], b1 = bias[c + 1];
            float* pa = acc[mi][ni];
            if (MODE == 0) {
#pragma unroll
                for (int rr = 0; rr < 2; rr++) {
                    int r = r0 + rr * 8;
                    float2 v;
                    v.x = fast_sig(pa[rr * 2 + 0] + b0);
                    v.y = fast_sig(pa[rr * 2 + 1] + b1);
                    if (col0 == 0) {
                        float2 h = *(const float2*)(&hbuf[(size_t)r * HID + c]);
                        v.x *= h.x; v.y *= h.y;
                    }
                    *(float2*)(&g_ru[(size_t)r * 256 + c]) = v;
                }
            } else {
#pragma unroll
                for (int rr = 0; rr < 2; rr++) {
                    int r = r0 + rr * 8;
                    float2 u = *(const float2*)(&g_ru[(size_t)r * 256 + 128 + c]);
                    float2 h = *(const float2*)(&hbuf[(size_t)r * HID + c]);
                    float2 o;
                    o.x = u.x * h.x + (1.f - u.x) * fast_tanh(pa[rr * 2 + 0] + b0);
                    o.y = u.y * h.y + (1.f - u.y) * fast_tanh(pa[rr * 2 + 1] + b1);
                    *(float2*)(&hbuf[(size_t)r * HID + c]) = o;
                    if (PROJ)
                        pr[rr] += o.x * Wp[c] + o.y * Wp[c + 1];
                }
            }
            if (MODE == 1 && PROJ && ni == 7) {
#pragma unroll
                for (int rr = 0; rr < 2; rr++) {
                    atomicAdd(&red[wm + mi * 16 + gr + rr * 8], pr[rr]);
                    pr[rr] = 0.f;
                }
            }
        }
    }
    if (PROJ) {
        __syncthreads();
        if (tid < 64) outp[row0 + tid] = red[tid] + bp[0];
    }
}

// ---------------- launch -----------------------------------------------------
extern "C" void kernel_launch(void* const* d_in, const int* in_sizes, int n_in,
                              void* d_out, int out_size) {
    (void)in_sizes; (void)n_in; (void)out_size;
    const float* ih  = (const float*)d_in[1];
    const float* S   = (const float*)d_in[2];
    const float* Wg0 = (const float*)d_in[3];
    const float* bg0 = (const float*)d_in[4];
    const float* Wc0 = (const float*)d_in[5];
    const float* bc0 = (const float*)d_in[6];
    const float* Wg1 = (const float*)d_in[7];
    const float* bg1 = (const float*)d_in[8];
    const float* Wc1 = (const float*)d_in[9];
    const float* bc1 = (const float*)d_in[10];
    const float* Wp  = (const float*)d_in[11];
    const float* bp  = (const float*)d_in[12];
    float* out = (float*)d_out;

    const int SMEM = 2 * STAGEB;   // 32768 B
    cudaFuncSetAttribute((const void*)k_gemm<0, 0, false>, cudaFuncAttributeMaxDynamicSharedMemorySize, SMEM);
    cudaFuncSetAttribute((const void*)k_gemm<0, 1, false>, cudaFuncAttributeMaxDynamicSharedMemorySize, SMEM);
    cudaFuncSetAttribute((const void*)k_gemm<1, 0, false>, cudaFuncAttributeMaxDynamicSharedMemorySize, SMEM);
    cudaFuncSetAttribute((const void*)k_gemm<1, 1, true>,  cudaFuncAttributeMaxDynamicSharedMemorySize, SMEM);

    k_init<<<NB_INIT, 256>>>(ih, S, Wg0, Wc0, Wg1, Wc1);

    for (int t = 0; t < SEQLEN; t++) {
        const float* xprev = t ? out + (size_t)(t - 1) * ROWS : nullptr;
        float* out_t = out + (size_t)t * ROWS;

        k_cheby0_gate<<<BATCH / 2, 256>>>(S, xprev);
        k_gemm<0, 0, false><<<dim3(304, 2), 128, SMEM>>>(bg0, nullptr, nullptr, nullptr);
        k_cheby_cand<0><<<BATCH / 2, 256>>>(S);
        k_gemm<1, 0, false><<<dim3(304, 1), 128, SMEM>>>(bc0, nullptr, nullptr, nullptr);

        k_cheby1_gate<<<BATCH / 2, 256>>>(S);
        k_gemm<0, 1, false><<<dim3(304, 2), 128, SMEM>>>(bg1, nullptr, nullptr, nullptr);
        k_cheby_cand<1><<<BATCH / 2, 256>>>(S);
        k_gemm<1, 1, true><<<dim3(304, 1), 128, SMEM>>>(bc1, Wp, bp, out_t);
    }
}